// round 14
// baseline (speedup 1.0000x reference)
#include <cuda_runtime.h>
#include <cuda_bf16.h>
#include <cuda_fp16.h>
#include <cuda_fp8.h>
#include <math.h>
#include <stdint.h>

#define Hdim 1024
#define Bdim 2
#define Sdim 4096
#define MTOT 8192
#define K2 2048
#define K3 3072
#define INV_SCALE 0.125f
#define LNEPS 1e-5f

// ---------------- scratch ----------------
__device__ __nv_bfloat16 g_xs[(long)MTOT*K3];      // x split hi|lo|hi
__device__ __half g_xcat[(long)MTOT*K2];           // [x_f16 | combined_f16]
__device__ float  g_qk32[2*(long)MTOT*Hdim];       // q then k, fp32
__device__ unsigned char g_qk8[2*(long)MTOT*Hdim]; // q8 then k8, e4m3
__device__ float  g_v[(long)MTOT*Hdim];
__device__ __half g_logh[(long)Bdim*Sdim*Sdim];    // fp16 approx logits (64 MB)
__device__ float  g_topv[MTOT*4];
__device__ int    g_topi[MTOT*4];
__device__ __half g_rh[(long)MTOT*Hdim];
__device__ float  g_cpre[(long)MTOT*Hdim];
__device__ float  g_comb[(long)MTOT*Hdim];
__device__ float  g_hpre[(long)MTOT*Hdim];
__device__ __half g_hs[(long)MTOT*Hdim];
__device__ __nv_bfloat16 g_wqk[(long)K3*K2];       // [3K, 2048] = [Wq|Wk] split hi;hi;lo
__device__ __half g_wh[3][(long)Hdim*Hdim];        // wv,wc,wg2 fp16 [K,N]
__device__ __half g_wg1h[(long)K2*Hdim];           // wg1 fp16 [2K,N]
__device__ float  g_bqk[K2];

// ---------------- helpers ----------------
__device__ __forceinline__ uint32_t s2u(const void* p){ return (uint32_t)__cvta_generic_to_shared(p); }

__device__ __forceinline__ void ldsm4(uint32_t& r0,uint32_t& r1,uint32_t& r2,uint32_t& r3, uint32_t a){
    asm volatile("ldmatrix.sync.aligned.m8n8.x4.shared.b16 {%0,%1,%2,%3},[%4];"
        :"=r"(r0),"=r"(r1),"=r"(r2),"=r"(r3):"r"(a));
}
__device__ __forceinline__ void ldsm4t(uint32_t& r0,uint32_t& r1,uint32_t& r2,uint32_t& r3, uint32_t a){
    asm volatile("ldmatrix.sync.aligned.m8n8.x4.trans.shared.b16 {%0,%1,%2,%3},[%4];"
        :"=r"(r0),"=r"(r1),"=r"(r2),"=r"(r3):"r"(a));
}
template<bool HALF>
__device__ __forceinline__ void mma16816(float* c, const uint32_t* a, const uint32_t* b){
    if (HALF)
        asm volatile("mma.sync.aligned.m16n8k16.row.col.f32.f16.f16.f32 "
            "{%0,%1,%2,%3},{%4,%5,%6,%7},{%8,%9},{%0,%1,%2,%3};"
            : "+f"(c[0]),"+f"(c[1]),"+f"(c[2]),"+f"(c[3])
            : "r"(a[0]),"r"(a[1]),"r"(a[2]),"r"(a[3]),"r"(b[0]),"r"(b[1]));
    else
        asm volatile("mma.sync.aligned.m16n8k16.row.col.f32.bf16.bf16.f32 "
            "{%0,%1,%2,%3},{%4,%5,%6,%7},{%8,%9},{%0,%1,%2,%3};"
            : "+f"(c[0]),"+f"(c[1]),"+f"(c[2]),"+f"(c[3])
            : "r"(a[0]),"r"(a[1]),"r"(a[2]),"r"(a[3]),"r"(b[0]),"r"(b[1]));
}
__device__ __forceinline__ void mma_fp8(float* c, const uint32_t* a, const uint32_t* b){
    asm volatile("mma.sync.aligned.m16n8k32.row.col.f32.e4m3.e4m3.f32 "
        "{%0,%1,%2,%3},{%4,%5,%6,%7},{%8,%9},{%0,%1,%2,%3};"
        : "+f"(c[0]),"+f"(c[1]),"+f"(c[2]),"+f"(c[3])
        : "r"(a[0]),"r"(a[1]),"r"(a[2]),"r"(a[3]),"r"(b[0]),"r"(b[1]));
}
__device__ __forceinline__ void cpa16(uint32_t dst, const void* src){
    asm volatile("cp.async.cg.shared.global [%0], [%1], 16;" :: "r"(dst), "l"(src));
}
__device__ __forceinline__ void cpa_commit(){ asm volatile("cp.async.commit_group;"); }
template<int N_> __device__ __forceinline__ void cpa_wait(){ asm volatile("cp.async.wait_group %0;"::"n"(N_)); }

__device__ __forceinline__ void split2(float v, __nv_bfloat16& h, __nv_bfloat16& l){
    h = __float2bfloat16(v);
    l = __float2bfloat16(v - __bfloat162float(h));
}

// ---------------- tensor-core GEMM, BK=64, 3-stage cp.async pipeline ----------------
// MODE 0: fp32 C = acc + bias[n]
// MODE 3: sg = sigmoid(acc+bias); C = sg*E1 + (1-sg)*E2
// MODE 7: qk dual: fp32 (Cptr) + e4m3 (P1), halves split at col 1024
#define BMt 128
#define BNt 128
#define BKt 64
#define ASTR 72
#define BSTRNN 136
#define NSTAGE 3

template<bool TRANSB, int MODE, bool HALF>
__global__ void __launch_bounds__(256, 2)
mma_gemm(const __nv_bfloat16* __restrict__ A, const __nv_bfloat16* __restrict__ B,
         const float* __restrict__ bias, const float* __restrict__ E1,
         const float* __restrict__ E2, void* __restrict__ Cptr,
         void* __restrict__ P1,
         int K, int N, int lda, int ldb, long sA, long sB, long sC, float alpha)
{
    constexpr int ASTAGE = BMt*ASTR*2;
    constexpr int BSTAGE = TRANSB ? (BNt*ASTR*2) : (BKt*BSTRNN*2);
    extern __shared__ char sm[];
    const uint32_t aBase = s2u(sm);
    const uint32_t bBase = aBase + NSTAGE*ASTAGE;

    const int tid  = threadIdx.x;
    const int lane = tid & 31;
    const int warp = tid >> 5;
    const int wm = warp & 1;
    const int wn = warp >> 1;
    const int m0 = blockIdx.y * BMt;
    const int n0 = blockIdx.x * BNt;

    const __nv_bfloat16* Ab = A + blockIdx.z*sA + (long)m0*lda;
    const __nv_bfloat16* Bb = TRANSB ? (B + blockIdx.z*sB + (long)n0*ldb) : (B + n0);

    float acc[4][4][4];
#pragma unroll
    for (int i=0;i<4;i++)
#pragma unroll
        for (int j=0;j<4;j++)
#pragma unroll
            for (int h=0;h<4;h++) acc[i][j][h] = 0.f;

    auto copyA = [&](int st, int k0){
        uint32_t base = aBase + st*ASTAGE;
#pragma unroll
        for (int l=0;l<4;l++){
            int id = tid + l*256; int r = id>>3; int c = (id&7)*8;
            cpa16(base + (r*ASTR + c)*2, Ab + (long)r*lda + k0 + c);
        }
    };
    auto copyB = [&](int st, int k0){
        uint32_t base = bBase + st*BSTAGE;
        if (TRANSB){
#pragma unroll
            for (int l=0;l<4;l++){
                int id = tid + l*256; int r = id>>3; int c = (id&7)*8;
                cpa16(base + (r*ASTR + c)*2, Bb + (long)r*ldb + k0 + c);
            }
        } else {
#pragma unroll
            for (int l=0;l<4;l++){
                int id = tid + l*256; int r = id>>4; int c = (id&15)*8;
                cpa16(base + (r*BSTRNN + c)*2, Bb + (long)(k0+r)*ldb + c);
            }
        }
    };

    const int nt = K / BKt;
#pragma unroll
    for (int s=0; s<NSTAGE-1; s++){
        copyA(s, s*BKt); copyB(s, s*BKt); cpa_commit();
    }

    int buf = 0;
    for (int t = 0; t < nt; t++){
        cpa_wait<NSTAGE-2>();
        __syncthreads();
        const uint32_t aS = aBase + buf*ASTAGE;
        const uint32_t bS = bBase + buf*BSTAGE;
#pragma unroll
        for (int ks=0; ks<4; ks++){
            uint32_t af[4][4];
#pragma unroll
            for (int mi=0; mi<4; mi++){
                int row = wm*64 + mi*16 + (lane&15);
                int col = ks*16 + ((lane>>4)<<3);
                ldsm4(af[mi][0],af[mi][1],af[mi][2],af[mi][3],
                      aS + (row*ASTR + col)*2);
            }
            uint32_t bf[4][2];
            if (TRANSB){
#pragma unroll
                for (int nj=0; nj<2; nj++){
                    int g = lane>>3;
                    int row = wn*32 + nj*16 + ((g>>1)<<3) + (lane&7);
                    int col = ks*16 + ((g&1)<<3);
                    uint32_t r0,r1,r2,r3;
                    ldsm4(r0,r1,r2,r3, bS + (row*ASTR + col)*2);
                    bf[nj*2][0]=r0; bf[nj*2][1]=r1; bf[nj*2+1][0]=r2; bf[nj*2+1][1]=r3;
                }
            } else {
#pragma unroll
                for (int nj=0; nj<2; nj++){
                    int row = ks*16 + (lane&15);
                    int col = wn*32 + nj*16 + ((lane>>4)<<3);
                    uint32_t r0,r1,r2,r3;
                    ldsm4t(r0,r1,r2,r3, bS + (row*BSTRNN + col)*2);
                    bf[nj*2][0]=r0; bf[nj*2][1]=r1; bf[nj*2+1][0]=r2; bf[nj*2+1][1]=r3;
                }
            }
#pragma unroll
            for (int mi=0;mi<4;mi++)
#pragma unroll
                for (int ni=0;ni<4;ni++)
                    mma16816<HALF>(acc[mi][ni], af[mi], bf[ni]);
        }
        int tn = t + NSTAGE-1;
        if (tn < nt){
            int st = buf + NSTAGE-1; if (st >= NSTAGE) st -= NSTAGE;
            copyA(st, tn*BKt); copyB(st, tn*BKt);
        }
        cpa_commit();
        buf = (buf+1 == NSTAGE) ? 0 : buf+1;
    }

    const long cb = blockIdx.z*sC;
#pragma unroll
    for (int mi=0;mi<4;mi++){
#pragma unroll
        for (int ni=0;ni<4;ni++){
#pragma unroll
            for (int h=0; h<2; h++){
                int row = m0 + wm*64 + mi*16 + (lane>>2) + h*8;
                int col = n0 + wn*32 + ni*8 + (lane&3)*2;
                float v0 = acc[mi][ni][h*2], v1 = acc[mi][ni][h*2+1];
                if (MODE == 0){
                    long idx = cb + (long)row*N + col;
                    float* C = (float*)Cptr;
                    C[idx]   = v0 + bias[col];
                    C[idx+1] = v1 + bias[col+1];
                } else if (MODE == 7){
                    float p0 = v0 + bias[col], p1 = v1 + bias[col+1];
                    long half_off = (long)(col >> 10) * ((long)MTOT*Hdim);
                    int c0 = col & 1023;
                    float2 o32; o32.x = p0; o32.y = p1;
                    *reinterpret_cast<float2*>((float*)Cptr + half_off + (long)row*Hdim + c0) = o32;
                    __nv_fp8x2_storage_t o8 = __nv_cvt_float2_to_fp8x2(o32, __NV_SATFINITE, __NV_E4M3);
                    *reinterpret_cast<__nv_fp8x2_storage_t*>((unsigned char*)P1 + half_off + (long)row*Hdim + c0) = o8;
                } else {  // MODE 3
                    long idx = cb + (long)row*N + col;
                    float* C = (float*)Cptr;
                    float p0 = v0 + bias[col],   p1 = v1 + bias[col+1];
                    float s0 = 1.f/(1.f+expf(-p0)), s1 = 1.f/(1.f+expf(-p1));
                    C[idx]   = s0*E1[idx]   + (1.f-s0)*E2[idx];
                    C[idx+1] = s1*E1[idx+1] + (1.f-s1)*E2[idx+1];
                }
            }
        }
    }
}

// ---------------- fp8 (e4m3) NT GEMM for approx logits ----------------
#define F8STR 80
#define F8STG (128*F8STR)

__global__ void __launch_bounds__(256, 2)
fp8_gemm(const unsigned char* __restrict__ A, const unsigned char* __restrict__ B,
         __half* __restrict__ C, int K, int N, long sA, long sB, long sC, float alpha)
{
    extern __shared__ char sm[];
    const uint32_t aBase = s2u(sm);
    const uint32_t bBase = aBase + NSTAGE*F8STG;

    const int tid  = threadIdx.x;
    const int lane = tid & 31;
    const int warp = tid >> 5;
    const int wm = warp & 1;
    const int wn = warp >> 1;
    const int m0 = blockIdx.y * 128;
    const int n0 = blockIdx.x * 128;

    const unsigned char* Ab = A + blockIdx.z*sA + (long)m0*K;
    const unsigned char* Bb = B + blockIdx.z*sB + (long)n0*K;

    float acc[4][4][4];
#pragma unroll
    for (int i=0;i<4;i++)
#pragma unroll
        for (int j=0;j<4;j++)
#pragma unroll
            for (int h=0;h<4;h++) acc[i][j][h] = 0.f;

    auto copyT = [&](uint32_t base, const unsigned char* src, int k0){
#pragma unroll
        for (int l=0;l<2;l++){
            int id = tid + l*256; int r = id>>2; int c = (id&3)*16;
            cpa16(base + r*F8STR + c, src + (long)r*K + k0 + c);
        }
    };

    const int nt = K / 64;
#pragma unroll
    for (int s=0; s<NSTAGE-1; s++){
        copyT(aBase + s*F8STG, Ab, s*64);
        copyT(bBase + s*F8STG, Bb, s*64);
        cpa_commit();
    }

    int buf = 0;
    for (int t = 0; t < nt; t++){
        cpa_wait<NSTAGE-2>();
        __syncthreads();
        const uint32_t aS = aBase + buf*F8STG;
        const uint32_t bS = bBase + buf*F8STG;
#pragma unroll
        for (int ks=0; ks<2; ks++){
            uint32_t af[4][4];
#pragma unroll
            for (int mi=0; mi<4; mi++){
                int row = wm*64 + mi*16 + (lane&15);
                int bc  = ks*32 + ((lane>>4)<<4);
                ldsm4(af[mi][0],af[mi][1],af[mi][2],af[mi][3],
                      aS + row*F8STR + bc);
            }
            uint32_t bf[4][2];
#pragma unroll
            for (int nj=0; nj<2; nj++){
                int g = lane>>3;
                int row = wn*32 + nj*16 + ((g>>1)<<3) + (lane&7);
                int bc  = ks*32 + ((g&1)<<4);
                uint32_t r0,r1,r2,r3;
                ldsm4(r0,r1,r2,r3, bS + row*F8STR + bc);
                bf[nj*2][0]=r0; bf[nj*2][1]=r1; bf[nj*2+1][0]=r2; bf[nj*2+1][1]=r3;
            }
#pragma unroll
            for (int mi=0;mi<4;mi++)
#pragma unroll
                for (int ni=0;ni<4;ni++)
                    mma_fp8(acc[mi][ni], af[mi], bf[ni]);
        }
        int tn = t + NSTAGE-1;
        if (tn < nt){
            int st = buf + NSTAGE-1; if (st >= NSTAGE) st -= NSTAGE;
            copyT(aBase + st*F8STG, Ab, tn*64);
            copyT(bBase + st*F8STG, Bb, tn*64);
        }
        cpa_commit();
        buf = (buf+1 == NSTAGE) ? 0 : buf+1;
    }

    const long cb = blockIdx.z*sC;
#pragma unroll
    for (int mi=0;mi<4;mi++){
#pragma unroll
        for (int ni=0;ni<4;ni++){
#pragma unroll
            for (int h=0; h<2; h++){
                int row = m0 + wm*64 + mi*16 + (lane>>2) + h*8;
                int col = n0 + wn*32 + ni*8 + (lane&3)*2;
                long idx = cb + (long)row*N + col;
                __half2 o = __floats2half2_rn(acc[mi][ni][h*2]*alpha, acc[mi][ni][h*2+1]*alpha);
                *reinterpret_cast<__half2*>(C + idx) = o;
            }
        }
    }
}

// ---------------- split x ----------------
__global__ void __launch_bounds__(256)
split_x_kernel(const float* __restrict__ in, __nv_bfloat16* __restrict__ xs,
               __half* __restrict__ xcat)
{
    long i = (long)blockIdx.x*256 + threadIdx.x;
    int m = (int)(i >> 10), k = (int)(i & 1023);
    float v = in[i];
    __nv_bfloat16 h,l; split2(v,h,l);
    long ob = (long)m*K3 + k;
    xs[ob] = h; xs[ob+1024] = l; xs[ob+2048] = h;
    xcat[(long)m*K2 + k] = __float2half(v);
}

// ---------------- fused weight prep ----------------
__global__ void __launch_bounds__(256)
prep_w_kernel(const float* __restrict__ Wq, const float* __restrict__ Wk,
              const float* __restrict__ Wv, const float* __restrict__ Wc,
              const float* __restrict__ Wg1, const float* __restrict__ Wg2,
              __nv_bfloat16* __restrict__ wqk, __half* __restrict__ wv,
              __half* __restrict__ wc, __half* __restrict__ wg2,
              __half* __restrict__ wg1h)
{
    long i = (long)blockIdx.x*256 + threadIdx.x;
    int kk = (int)(i >> 10), n = (int)(i & 1023);
    float vq = Wq[i], vk = Wk[i];
    __nv_bfloat16 hq,lq,hk,lk; split2(vq,hq,lq); split2(vk,hk,lk);
    const long BLK = (long)1024*K2;
    long o = (long)kk*K2 + n;
    wqk[o]       = hq; wqk[o+1024]       = hk;
    wqk[o+BLK]   = hq; wqk[o+BLK+1024]   = hk;
    wqk[o+2*BLK] = lq; wqk[o+2*BLK+1024] = lk;
    wv[i]  = __float2half(Wv[i]);
    wc[i]  = __float2half(Wc[i]);
    wg2[i] = __float2half(Wg2[i]);
    wg1h[i] = __float2half(Wg1[i]);
    wg1h[i + (long)1024*1024] = __float2half(Wg1[i + (long)1024*1024]);
}

__global__ void __launch_bounds__(256)
bqk_kernel(const float* __restrict__ bq, const float* __restrict__ bk, float* __restrict__ out)
{
    int i = blockIdx.x*256 + threadIdx.x;
    out[i] = (i < 1024) ? bq[i] : bk[i-1024];
}

// ---------------- top-k helpers ----------------
__device__ __forceinline__ void ins4(float v, int id, float tv[4], int ti[4]) {
    if (v <= tv[3]) return;
    if (v > tv[0]) { tv[3]=tv[2]; ti[3]=ti[2]; tv[2]=tv[1]; ti[2]=ti[1];
                     tv[1]=tv[0]; ti[1]=ti[0]; tv[0]=v; ti[0]=id; }
    else if (v > tv[1]) { tv[3]=tv[2]; ti[3]=ti[2]; tv[2]=tv[1]; ti[2]=ti[1]; tv[1]=v; ti[1]=id; }
    else if (v > tv[2]) { tv[3]=tv[2]; ti[3]=ti[2]; tv[2]=v; ti[2]=id; }
    else { tv[3]=v; ti[3]=id; }
}
__device__ __forceinline__ void ins16(float v, int id, float* tv, int* ti) {
    if (v <= tv[15]) return;
    tv[15] = v; ti[15] = id;
#pragma unroll
    for (int j=15; j>0; j--){
        if (tv[j] > tv[j-1]){
            float tf=tv[j]; tv[j]=tv[j-1]; tv[j-1]=tf;
            int tii=ti[j]; ti[j]=ti[j-1]; ti[j-1]=tii;
        }
    }
}

// ---------------- top-16 approx (fp16 logits) + exact fp32 rescue -> top-4 ----------------
__global__ void __launch_bounds__(128)
topk_rescue(const __half* __restrict__ logits, const float* __restrict__ q,
            const float* __restrict__ k, float* __restrict__ topv, int* __restrict__ topi)
{
    const int m = blockIdx.x;
    const int tid = threadIdx.x;
    const __half2* p2 = reinterpret_cast<const __half2*>(logits + (long)m * Sdim);

    float tv[16]; int ti[16];
#pragma unroll
    for (int j=0;j<16;j++){ tv[j]=-1e30f; ti[j]=-1; }
    for (int j = tid; j < Sdim/2; j += 128){
        __half2 hv = p2[j];
        ins16(__low2float(hv),  2*j,   tv, ti);
        ins16(__high2float(hv), 2*j+1, tv, ti);
    }

    __shared__ float sv[128*16];
    __shared__ int   si[128*16];
#pragma unroll
    for (int j=0;j<16;j++){ sv[tid*16+j]=tv[j]; si[tid*16+j]=ti[j]; }
    __syncthreads();

    // stage 2: 32 lanes each merge 4 thread-lists of 16
    if (tid < 32){
        float mv[16]; int mi[16];
#pragma unroll
        for (int j=0;j<16;j++){ mv[j]=-1e30f; mi[j]=-1; }
        for (int s=0;s<4;s++){
            int base = (tid + s*32)*16;
#pragma unroll
            for (int j=0;j<16;j++) ins16(sv[base+j], si[base+j], mv, mi);
        }
#pragma unroll
        for (int j=0;j<16;j++){ sv[tid*16+j]=mv[j]; si[tid*16+j]=mi[j]; }
    }
    __syncthreads();

    // stage 3: 8 lanes merge 4 lists each -> 8 lists
    if (tid < 8){
        float mv[16]; int mi[16];
#pragma unroll
        for (int j=0;j<16;j++){ mv[j]=-1e30f; mi[j]=-1; }
        for (int s=0;s<4;s++){
            int base = (tid + s*8)*16;
#pragma unroll
            for (int j=0;j<16;j++) ins16(sv[base+j], si[base+j], mv, mi);
        }
#pragma unroll
        for (int j=0;j<16;j++){ sv[tid*16+j]=mv[j]; si[tid*16+j]=mi[j]; }
    }
    __syncthreads();

    __shared__ int cands[16];
    if (tid == 0){
        float rv[16]; int ri[16];
#pragma unroll
        for (int j=0;j<16;j++){ rv[j]=-1e30f; ri[j]=-1; }
        for (int c=0;c<8*16;c++) ins16(sv[c], si[c], rv, ri);
#pragma unroll
        for (int j=0;j<16;j++) cands[j] = ri[j];
    }
    __syncthreads();

    __shared__ float qrow[Hdim];
    const float* qr = q + (long)m*Hdim;
    for (int j = tid; j < Hdim; j += 128) qrow[j] = qr[j];
    __syncthreads();

    const int b = m >> 12;
    const int warp = tid >> 5, lane = tid & 31;
    __shared__ float exact[16];
#pragma unroll
    for (int cc=0; cc<4; cc++){
        int c = warp*4 + cc;
        const float* kr = k + ((long)b*Sdim + cands[c])*Hdim;
        float s = 0.f;
        for (int j = lane; j < Hdim; j += 32) s += qrow[j]*kr[j];
#pragma unroll
        for (int o=16;o>0;o>>=1) s += __shfl_down_sync(0xffffffffu, s, o);
        if (lane == 0) exact[c] = s * INV_SCALE;
    }
    __syncthreads();

    if (tid == 0){
        float rv[4] = {-1e30f,-1e30f,-1e30f,-1e30f};
        int   ri[4] = {-1,-1,-1,-1};
#pragma unroll
        for (int c=0;c<16;c++) ins4(exact[c], cands[c], rv, ri);
#pragma unroll
        for (int j=0;j<4;j++){ topv[m*4+j]=rv[j]; topi[m*4+j]=ri[j]; }
    }
}

// ---------------- softmax + gather-weighted V -> fp16 routed ----------------
__global__ void __launch_bounds__(256)
route_kernel(const float* __restrict__ v, const float* __restrict__ topv,
             const int* __restrict__ topi, const float* __restrict__ temp,
             __half* __restrict__ rh)
{
    const int m = blockIdx.x;
    const int b = m >> 12;
    const float t = temp[0];
    float v0 = topv[m*4+0], v1 = topv[m*4+1], v2 = topv[m*4+2], v3 = topv[m*4+3];
    float mx = fmaxf(fmaxf(v0,v1), fmaxf(v2,v3));
    float e0 = expf((v0-mx)/t), e1 = expf((v1-mx)/t);
    float e2 = expf((v2-mx)/t), e3 = expf((v3-mx)/t);
    float inv = 1.f/(e0+e1+e2+e3);
    e0*=inv; e1*=inv; e2*=inv; e3*=inv;

    const float* vb = v + (long)b*Sdim*Hdim;
    int i0=topi[m*4+0], i1=topi[m*4+1], i2=topi[m*4+2], i3=topi[m*4+3];
    const float4* r0 = reinterpret_cast<const float4*>(vb + (long)i0*Hdim);
    const float4* r1 = reinterpret_cast<const float4*>(vb + (long)i1*Hdim);
    const float4* r2 = reinterpret_cast<const float4*>(vb + (long)i2*Hdim);
    const float4* r3 = reinterpret_cast<const float4*>(vb + (long)i3*Hdim);

    int c = threadIdx.x;
    float4 a = r0[c], bb = r1[c], cc = r2[c], dd = r3[c];
    float o[4];
    o[0] = e0*a.x + e1*bb.x + e2*cc.x + e3*dd.x;
    o[1] = e0*a.y + e1*bb.y + e2*cc.y + e3*dd.y;
    o[2] = e0*a.z + e1*bb.z + e2*cc.z + e3*dd.z;
    o[3] = e0*a.w + e1*bb.w + e2*cc.w + e3*dd.w;
    long ob = (long)m*Hdim + c*4;
#pragma unroll
    for (int j=0;j<4;j++) rh[ob+j] = __float2half(o[j]);
}

// ---------------- LayerNorm (+gelu) ----------------
template<int GELU>
__global__ void __launch_bounds__(256)
ln_kernel(const float* __restrict__ in, const float* __restrict__ g,
          const float* __restrict__ b, float* __restrict__ outf,
          __half* __restrict__ outh, int ostride)
{
    const int m = blockIdx.x;
    const int c = threadIdx.x;
    float4 x4 = reinterpret_cast<const float4*>(in + (long)m*Hdim)[c];
    float s  = x4.x + x4.y + x4.z + x4.w;
    float ss = x4.x*x4.x + x4.y*x4.y + x4.z*x4.z + x4.w*x4.w;
#pragma unroll
    for (int o=16;o>0;o>>=1){
        s  += __shfl_down_sync(0xffffffffu, s,  o);
        ss += __shfl_down_sync(0xffffffffu, ss, o);
    }
    __shared__ float red[2][8];
    int warp = c>>5, lane = c&31;
    if (lane==0){ red[0][warp]=s; red[1][warp]=ss; }
    __syncthreads();
    if (c==0){
        float S_=0.f, SS_=0.f;
#pragma unroll
        for (int w=0;w<8;w++){ S_+=red[0][w]; SS_+=red[1][w]; }
        red[0][0]=S_; red[1][0]=SS_;
    }
    __syncthreads();
    float mu  = red[0][0]*(1.f/Hdim);
    float var = red[1][0]*(1.f/Hdim) - mu*mu;
    float rsd = rsqrtf(var + LNEPS);
    float4 g4 = reinterpret_cast<const float4*>(g)[c];
    float4 b4 = reinterpret_cast<const float4*>(b)[c];
    float y[4];
    y[0] = (x4.x-mu)*rsd*g4.x + b4.x;
    y[1] = (x4.y-mu)*rsd*g4.y + b4.y;
    y[2] = (x4.z-mu)*rsd*g4.z + b4.z;
    y[3] = (x4.w-mu)*rsd*g4.w + b4.w;
    if (GELU){
#pragma unroll
        for (int j=0;j<4;j++) y[j] = 0.5f*y[j]*(1.f + erff(y[j]*0.70710678118f));
    }
    if (outf){
        float4 yo; yo.x=y[0]; yo.y=y[1]; yo.z=y[2]; yo.w=y[3];
        reinterpret_cast<float4*>(outf + (long)m*Hdim)[c] = yo;
    }
    long ob = (long)m*ostride + c*4;
#pragma unroll
    for (int j=0;j<4;j++) outh[ob+j] = __float2half(y[j]);
}

// ---------------- launch ----------------
extern "C" void kernel_launch(void* const* d_in, const int* in_sizes, int n_in,
                              void* d_out, int out_size)
{
    const float* x    = (const float*)d_in[0];
    const float* Wq   = (const float*)d_in[1];
    const float* bq   = (const float*)d_in[2];
    const float* Wk   = (const float*)d_in[3];
    const float* bk   = (const float*)d_in[4];
    const float* Wv   = (const float*)d_in[5];
    const float* bv   = (const float*)d_in[6];
    const float* Wc   = (const float*)d_in[7];
    const float* bc   = (const float*)d_in[8];
    const float* ln_g = (const float*)d_in[9];
    const float* ln_b = (const float*)d_in[10];
    const float* Wg1  = (const float*)d_in[11];
    const float* bg1  = (const float*)d_in[12];
    const float* gln_g= (const float*)d_in[13];
    const float* gln_b= (const float*)d_in[14];
    const float* Wg2  = (const float*)d_in[15];
    const float* bg2  = (const float*)d_in[16];
    const float* temp = (const float*)d_in[17];
    float* out = (float*)d_out;

    __nv_bfloat16 *xs_p, *wqk_p;
    __half *xcat_p, *logh_p, *rh_p, *hs_p, *wh_p, *wg1h_p;
    unsigned char *qk8_p;
    float *qk32_p, *v_p, *topv_p, *cpre_p, *comb_p, *hpre_p, *bqk_p;
    int *topi_p;
    cudaGetSymbolAddress((void**)&xs_p,    g_xs);
    cudaGetSymbolAddress((void**)&xcat_p,  g_xcat);
    cudaGetSymbolAddress((void**)&qk32_p,  g_qk32);
    cudaGetSymbolAddress((void**)&qk8_p,   g_qk8);
    cudaGetSymbolAddress((void**)&v_p,     g_v);
    cudaGetSymbolAddress((void**)&logh_p,  g_logh);
    cudaGetSymbolAddress((void**)&topv_p,  g_topv);
    cudaGetSymbolAddress((void**)&topi_p,  g_topi);
    cudaGetSymbolAddress((void**)&rh_p,    g_rh);
    cudaGetSymbolAddress((void**)&cpre_p,  g_cpre);
    cudaGetSymbolAddress((void**)&comb_p,  g_comb);
    cudaGetSymbolAddress((void**)&hpre_p,  g_hpre);
    cudaGetSymbolAddress((void**)&hs_p,    g_hs);
    cudaGetSymbolAddress((void**)&wqk_p,   g_wqk);
    cudaGetSymbolAddress((void**)&wh_p,    g_wh);
    cudaGetSymbolAddress((void**)&wg1h_p,  g_wg1h);
    cudaGetSymbolAddress((void**)&bqk_p,   g_bqk);

    float* q_p = qk32_p;
    float* k_p = qk32_p + (long)MTOT*Hdim;
    unsigned char* q8_p = qk8_p;
    unsigned char* k8_p = qk8_p + (long)MTOT*Hdim;
    __half *wv_p = wh_p, *wc_p = wh_p + (long)Hdim*Hdim, *wg2_p = wh_p + 2*(long)Hdim*Hdim;

    // prep
    split_x_kernel<<<MTOT*Hdim/256, 256>>>(x, xs_p, xcat_p);
    prep_w_kernel<<<Hdim*Hdim/256, 256>>>(Wq, Wk, Wv, Wc, Wg1, Wg2,
                                          wqk_p, wv_p, wc_p, wg2_p, wg1h_p);
    bqk_kernel<<<K2/256, 256>>>(bq, bk, bqk_p);

    dim3 gNN(Hdim/BNt, MTOT/BMt, 1);       // (8, 64)
    dim3 gQK(K2/BNt, MTOT/BMt, 1);         // (16, 64)
    dim3 gNT(Sdim/BNt, Sdim/BMt, Bdim);    // (32, 32, 2)

    const int smemNN = NSTAGE*(BMt*ASTR*2 + BKt*BSTRNN*2);   // 107520
    const int smemF8 = NSTAGE*2*F8STG;                        // 61440

    cudaFuncSetAttribute((const void*)mma_gemm<false,7,false>, cudaFuncAttributeMaxDynamicSharedMemorySize, smemNN);
    cudaFuncSetAttribute((const void*)mma_gemm<false,0,true>,  cudaFuncAttributeMaxDynamicSharedMemorySize, smemNN);
    cudaFuncSetAttribute((const void*)mma_gemm<false,3,true>,  cudaFuncAttributeMaxDynamicSharedMemorySize, smemNN);
    cudaFuncSetAttribute((const void*)fp8_gemm,                cudaFuncAttributeMaxDynamicSharedMemorySize, smemF8);

    // fused q|k (bf16x3, K=3072, N=2048) -> fp32 q,k + e4m3 q8,k8
    mma_gemm<false,7,false><<<gQK,256,smemNN>>>(xs_p, wqk_p, bqk_p, nullptr, nullptr,
                                   qk32_p, qk8_p, K3, K2, K3, K2, 0,0,0, 1.f);

    // v (fp16 single pass, K=1024)
    mma_gemm<false,0,true><<<gNN,256,smemNN>>>((const __nv_bfloat16*)xcat_p, (const __nv_bfloat16*)wv_p,
                                   bv, nullptr, nullptr, v_p, nullptr,
                                   Hdim, Hdim, K2, Hdim, 0,0,0, 1.f);

    // approx logits (e4m3, K=1024) -> fp16 logits buffer
    fp8_gemm<<<gNT,256,smemF8>>>(q8_p, k8_p, logh_p, Hdim, Sdim,
                                 (long)Sdim*Hdim, (long)Sdim*Hdim, (long)Sdim*Sdim, INV_SCALE);

    // top-16 approx -> exact fp32 rescue -> top-4
    topk_rescue<<<MTOT,128>>>(logh_p, q_p, k_p, topv_p, topi_p);
    route_kernel<<<MTOT,256>>>(v_p, topv_p, topi_p, temp, rh_p);

    // combined = LN(routed @ Wc + bc); fp16 into xcat second half
    mma_gemm<false,0,true><<<gNN,256,smemNN>>>((const __nv_bfloat16*)rh_p, (const __nv_bfloat16*)wc_p,
                                   bc, nullptr, nullptr, cpre_p, nullptr,
                                   Hdim, Hdim, Hdim, Hdim, 0,0,0, 1.f);
    ln_kernel<0><<<MTOT,256>>>(cpre_p, ln_g, ln_b, comb_p, xcat_p + Hdim, K2);

    // hpre = [x|combined] @ Wg1 + bg1  (fp16, K=2048)
    mma_gemm<false,0,true><<<gNN,256,smemNN>>>((const __nv_bfloat16*)xcat_p, (const __nv_bfloat16*)wg1h_p,
                                   bg1, nullptr, nullptr, hpre_p, nullptr,
                                   K2, Hdim, K2, Hdim, 0,0,0, 1.f);

    // h = gelu(LN(hpre))
    ln_kernel<1><<<MTOT,256>>>(hpre_p, gln_g, gln_b, nullptr, hs_p, Hdim);

    // out = sigmoid(h @ Wg2 + bg2) * combined + (1-s) * x
    mma_gemm<false,3,true><<<gNN,256,smemNN>>>((const __nv_bfloat16*)hs_p, (const __nv_bfloat16*)wg2_p,
                                   bg2, comb_p, x, out, nullptr,
                                   Hdim, Hdim, Hdim, Hdim, 0,0,0, 1.f);
}

// round 15
// speedup vs baseline: 1.5381x; 1.5381x over previous
#include <cuda_runtime.h>
#include <cuda_bf16.h>
#include <cuda_fp16.h>
#include <math.h>
#include <stdint.h>

#define Hdim 1024
#define Bdim 2
#define Sdim 4096
#define MTOT 8192
#define K2 2048
#define K3 3072
#define INV_SCALE 0.125f
#define LNEPS 1e-5f

// ---------------- scratch ----------------
__device__ __nv_bfloat16 g_xs[(long)MTOT*K3];      // x split hi|lo|hi
__device__ __half g_xcat[(long)MTOT*K2];           // [x_f16 | combined_f16]
__device__ float  g_qk32[2*(long)MTOT*Hdim];       // q then k, fp32 (rescue precision)
__device__ __half g_qkh[2*(long)MTOT*Hdim];        // qh then kh
__device__ __half g_vh[(long)MTOT*Hdim];           // v fp16
__device__ __half g_logh[(long)Bdim*Sdim*Sdim];    // fp16 approx logits (64 MB)
__device__ float  g_topv[MTOT*4];
__device__ int    g_topi[MTOT*4];
__device__ __half g_rh[(long)MTOT*Hdim];
__device__ __half g_cpreh[(long)MTOT*Hdim];
__device__ __half g_combh[(long)MTOT*Hdim];
__device__ __half g_hpreh[(long)MTOT*Hdim];
__device__ __half g_hs[(long)MTOT*Hdim];
__device__ __nv_bfloat16 g_wqk[(long)K3*K2];       // [3K, 2048] = [Wq|Wk] split hi;hi;lo
__device__ __half g_wh[3][(long)Hdim*Hdim];        // wv,wc,wg2 fp16 [K,N]
__device__ __half g_wg1h[(long)K2*Hdim];           // wg1 fp16 [2K,N]
__device__ float  g_bqk[K2];

// ---------------- helpers ----------------
__device__ __forceinline__ uint32_t s2u(const void* p){ return (uint32_t)__cvta_generic_to_shared(p); }

__device__ __forceinline__ void ldsm4(uint32_t& r0,uint32_t& r1,uint32_t& r2,uint32_t& r3, uint32_t a){
    asm volatile("ldmatrix.sync.aligned.m8n8.x4.shared.b16 {%0,%1,%2,%3},[%4];"
        :"=r"(r0),"=r"(r1),"=r"(r2),"=r"(r3):"r"(a));
}
__device__ __forceinline__ void ldsm4t(uint32_t& r0,uint32_t& r1,uint32_t& r2,uint32_t& r3, uint32_t a){
    asm volatile("ldmatrix.sync.aligned.m8n8.x4.trans.shared.b16 {%0,%1,%2,%3},[%4];"
        :"=r"(r0),"=r"(r1),"=r"(r2),"=r"(r3):"r"(a));
}
template<bool HALF>
__device__ __forceinline__ void mma16816(float* c, const uint32_t* a, const uint32_t* b){
    if (HALF)
        asm volatile("mma.sync.aligned.m16n8k16.row.col.f32.f16.f16.f32 "
            "{%0,%1,%2,%3},{%4,%5,%6,%7},{%8,%9},{%0,%1,%2,%3};"
            : "+f"(c[0]),"+f"(c[1]),"+f"(c[2]),"+f"(c[3])
            : "r"(a[0]),"r"(a[1]),"r"(a[2]),"r"(a[3]),"r"(b[0]),"r"(b[1]));
    else
        asm volatile("mma.sync.aligned.m16n8k16.row.col.f32.bf16.bf16.f32 "
            "{%0,%1,%2,%3},{%4,%5,%6,%7},{%8,%9},{%0,%1,%2,%3};"
            : "+f"(c[0]),"+f"(c[1]),"+f"(c[2]),"+f"(c[3])
            : "r"(a[0]),"r"(a[1]),"r"(a[2]),"r"(a[3]),"r"(b[0]),"r"(b[1]));
}
__device__ __forceinline__ void cpa16(uint32_t dst, const void* src){
    asm volatile("cp.async.cg.shared.global [%0], [%1], 16;" :: "r"(dst), "l"(src));
}
__device__ __forceinline__ void cpa_commit(){ asm volatile("cp.async.commit_group;"); }
template<int N_> __device__ __forceinline__ void cpa_wait(){ asm volatile("cp.async.wait_group %0;"::"n"(N_)); }

__device__ __forceinline__ void split2(float v, __nv_bfloat16& h, __nv_bfloat16& l){
    h = __float2bfloat16(v);
    l = __float2bfloat16(v - __bfloat162float(h));
}

// ---------------- tensor-core GEMM, BK=64, 3-stage cp.async pipeline ----------------
// BM=128, BN=128, BK=64, 256 threads (8 warps 2x4), warp tile 64x32.
// MODE 2: fp16 C = acc * alpha            (logits)
// MODE 3: sg = sigmoid(acc+bias); fp32 C = sg*E1h + (1-sg)*E2   (E1 fp16, E2 fp32)
// MODE 4: fp16 C = acc + bias[n]
// MODE 7: qk dual: fp32 (Cptr) + fp16 (P1), halves split at col 1024
#define BMt 128
#define BNt 128
#define BKt 64
#define ASTR 72      // 64+8 elems: conflict-free ldmatrix
#define BSTRNN 136   // 128+8 elems
#define NSTAGE 3

template<bool TRANSB, int MODE, bool HALF>
__global__ void __launch_bounds__(256, 2)
mma_gemm(const __nv_bfloat16* __restrict__ A, const __nv_bfloat16* __restrict__ B,
         const float* __restrict__ bias, const __half* __restrict__ E1,
         const float* __restrict__ E2, void* __restrict__ Cptr,
         void* __restrict__ P1,
         int K, int N, int lda, int ldb, long sA, long sB, long sC, float alpha)
{
    constexpr int ASTAGE = BMt*ASTR*2;
    constexpr int BSTAGE = TRANSB ? (BNt*ASTR*2) : (BKt*BSTRNN*2);
    extern __shared__ char sm[];
    const uint32_t aBase = s2u(sm);
    const uint32_t bBase = aBase + NSTAGE*ASTAGE;

    const int tid  = threadIdx.x;
    const int lane = tid & 31;
    const int warp = tid >> 5;
    const int wm = warp & 1;
    const int wn = warp >> 1;
    const int m0 = blockIdx.y * BMt;
    const int n0 = blockIdx.x * BNt;

    const __nv_bfloat16* Ab = A + blockIdx.z*sA + (long)m0*lda;
    const __nv_bfloat16* Bb = TRANSB ? (B + blockIdx.z*sB + (long)n0*ldb) : (B + n0);

    float acc[4][4][4];
#pragma unroll
    for (int i=0;i<4;i++)
#pragma unroll
        for (int j=0;j<4;j++)
#pragma unroll
            for (int h=0;h<4;h++) acc[i][j][h] = 0.f;

    auto copyA = [&](int st, int k0){
        uint32_t base = aBase + st*ASTAGE;
#pragma unroll
        for (int l=0;l<4;l++){
            int id = tid + l*256; int r = id>>3; int c = (id&7)*8;
            cpa16(base + (r*ASTR + c)*2, Ab + (long)r*lda + k0 + c);
        }
    };
    auto copyB = [&](int st, int k0){
        uint32_t base = bBase + st*BSTAGE;
        if (TRANSB){
#pragma unroll
            for (int l=0;l<4;l++){
                int id = tid + l*256; int r = id>>3; int c = (id&7)*8;
                cpa16(base + (r*ASTR + c)*2, Bb + (long)r*ldb + k0 + c);
            }
        } else {
#pragma unroll
            for (int l=0;l<4;l++){
                int id = tid + l*256; int r = id>>4; int c = (id&15)*8;
                cpa16(base + (r*BSTRNN + c)*2, Bb + (long)(k0+r)*ldb + c);
            }
        }
    };

    const int nt = K / BKt;
#pragma unroll
    for (int s=0; s<NSTAGE-1; s++){
        copyA(s, s*BKt); copyB(s, s*BKt); cpa_commit();
    }

    int buf = 0;
    for (int t = 0; t < nt; t++){
        cpa_wait<NSTAGE-2>();
        __syncthreads();
        const uint32_t aS = aBase + buf*ASTAGE;
        const uint32_t bS = bBase + buf*BSTAGE;
#pragma unroll
        for (int ks=0; ks<4; ks++){
            uint32_t af[4][4];
#pragma unroll
            for (int mi=0; mi<4; mi++){
                int row = wm*64 + mi*16 + (lane&15);
                int col = ks*16 + ((lane>>4)<<3);
                ldsm4(af[mi][0],af[mi][1],af[mi][2],af[mi][3],
                      aS + (row*ASTR + col)*2);
            }
            uint32_t bf[4][2];
            if (TRANSB){
#pragma unroll
                for (int nj=0; nj<2; nj++){
                    int g = lane>>3;
                    int row = wn*32 + nj*16 + ((g>>1)<<3) + (lane&7);
                    int col = ks*16 + ((g&1)<<3);
                    uint32_t r0,r1,r2,r3;
                    ldsm4(r0,r1,r2,r3, bS + (row*ASTR + col)*2);
                    bf[nj*2][0]=r0; bf[nj*2][1]=r1; bf[nj*2+1][0]=r2; bf[nj*2+1][1]=r3;
                }
            } else {
#pragma unroll
                for (int nj=0; nj<2; nj++){
                    int row = ks*16 + (lane&15);
                    int col = wn*32 + nj*16 + ((lane>>4)<<3);
                    uint32_t r0,r1,r2,r3;
                    ldsm4t(r0,r1,r2,r3, bS + (row*BSTRNN + col)*2);
                    bf[nj*2][0]=r0; bf[nj*2][1]=r1; bf[nj*2+1][0]=r2; bf[nj*2+1][1]=r3;
                }
            }
#pragma unroll
            for (int mi=0;mi<4;mi++)
#pragma unroll
                for (int ni=0;ni<4;ni++)
                    mma16816<HALF>(acc[mi][ni], af[mi], bf[ni]);
        }
        int tn = t + NSTAGE-1;
        if (tn < nt){
            int st = buf + NSTAGE-1; if (st >= NSTAGE) st -= NSTAGE;
            copyA(st, tn*BKt); copyB(st, tn*BKt);
        }
        cpa_commit();
        buf = (buf+1 == NSTAGE) ? 0 : buf+1;
    }

    const long cb = blockIdx.z*sC;
#pragma unroll
    for (int mi=0;mi<4;mi++){
#pragma unroll
        for (int ni=0;ni<4;ni++){
#pragma unroll
            for (int h=0; h<2; h++){
                int row = m0 + wm*64 + mi*16 + (lane>>2) + h*8;
                int col = n0 + wn*32 + ni*8 + (lane&3)*2;
                float v0 = acc[mi][ni][h*2], v1 = acc[mi][ni][h*2+1];
                if (MODE == 2){
                    long idx = cb + (long)row*N + col;
                    __half2 o = __floats2half2_rn(v0*alpha, v1*alpha);
                    *reinterpret_cast<__half2*>((__half*)Cptr + idx) = o;
                } else if (MODE == 4){
                    long idx = cb + (long)row*N + col;
                    __half2 o = __floats2half2_rn(v0 + bias[col], v1 + bias[col+1]);
                    *reinterpret_cast<__half2*>((__half*)Cptr + idx) = o;
                } else if (MODE == 7){
                    float p0 = v0 + bias[col], p1 = v1 + bias[col+1];
                    long half_off = (long)(col >> 10) * ((long)MTOT*Hdim);
                    int c0 = col & 1023;
                    float2 o32; o32.x = p0; o32.y = p1;
                    *reinterpret_cast<float2*>((float*)Cptr + half_off + (long)row*Hdim + c0) = o32;
                    __half2 o16 = __floats2half2_rn(p0, p1);
                    *reinterpret_cast<__half2*>((__half*)P1 + half_off + (long)row*Hdim + c0) = o16;
                } else {  // MODE 3
                    long idx = cb + (long)row*N + col;
                    float* C = (float*)Cptr;
                    float p0 = v0 + bias[col],   p1 = v1 + bias[col+1];
                    float s0 = 1.f/(1.f+expf(-p0)), s1 = 1.f/(1.f+expf(-p1));
                    C[idx]   = s0*__half2float(E1[idx])   + (1.f-s0)*E2[idx];
                    C[idx+1] = s1*__half2float(E1[idx+1]) + (1.f-s1)*E2[idx+1];
                }
            }
        }
    }
}

// ---------------- split x: bf16x3 (stride K3) + fp16 into xcat ----------------
__global__ void __launch_bounds__(256)
split_x_kernel(const float* __restrict__ in, __nv_bfloat16* __restrict__ xs,
               __half* __restrict__ xcat)
{
    long i = (long)blockIdx.x*256 + threadIdx.x;
    int m = (int)(i >> 10), k = (int)(i & 1023);
    float v = in[i];
    __nv_bfloat16 h,l; split2(v,h,l);
    long ob = (long)m*K3 + k;
    xs[ob] = h; xs[ob+1024] = l; xs[ob+2048] = h;
    xcat[(long)m*K2 + k] = __float2half(v);
}

// ---------------- fused weight prep ----------------
__global__ void __launch_bounds__(256)
prep_w_kernel(const float* __restrict__ Wq, const float* __restrict__ Wk,
              const float* __restrict__ Wv, const float* __restrict__ Wc,
              const float* __restrict__ Wg1, const float* __restrict__ Wg2,
              const float* __restrict__ bq, const float* __restrict__ bk,
              __nv_bfloat16* __restrict__ wqk, __half* __restrict__ wv,
              __half* __restrict__ wc, __half* __restrict__ wg2,
              __half* __restrict__ wg1h, float* __restrict__ bqk)
{
    long i = (long)blockIdx.x*256 + threadIdx.x;
    int kk = (int)(i >> 10), n = (int)(i & 1023);
    float vq = Wq[i], vk = Wk[i];
    __nv_bfloat16 hq,lq,hk,lk; split2(vq,hq,lq); split2(vk,hk,lk);
    const long BLK = (long)1024*K2;
    long o = (long)kk*K2 + n;
    wqk[o]       = hq; wqk[o+1024]       = hk;
    wqk[o+BLK]   = hq; wqk[o+BLK+1024]   = hk;
    wqk[o+2*BLK] = lq; wqk[o+2*BLK+1024] = lk;
    wv[i]  = __float2half(Wv[i]);
    wc[i]  = __float2half(Wc[i]);
    wg2[i] = __float2half(Wg2[i]);
    wg1h[i] = __float2half(Wg1[i]);
    wg1h[i + (long)1024*1024] = __float2half(Wg1[i + (long)1024*1024]);
    if (i < 1024){ bqk[i] = bq[i]; bqk[i+1024] = bk[i]; }
}

// ---------------- top-k helpers ----------------
__device__ __forceinline__ void ins4(float v, int id, float tv[4], int ti[4]) {
    if (v <= tv[3]) return;
    if (v > tv[0]) { tv[3]=tv[2]; ti[3]=ti[2]; tv[2]=tv[1]; ti[2]=ti[1];
                     tv[1]=tv[0]; ti[1]=ti[0]; tv[0]=v; ti[0]=id; }
    else if (v > tv[1]) { tv[3]=tv[2]; ti[3]=ti[2]; tv[2]=tv[1]; ti[2]=ti[1]; tv[1]=v; ti[1]=id; }
    else if (v > tv[2]) { tv[3]=tv[2]; ti[3]=ti[2]; tv[2]=v; ti[2]=id; }
    else { tv[3]=v; ti[3]=id; }
}
__device__ __forceinline__ void ins8(float v, int id, float* tv, int* ti) {
    if (v <= tv[7]) return;
    tv[7] = v; ti[7] = id;
#pragma unroll
    for (int j=7; j>0; j--){
        if (tv[j] > tv[j-1]){
            float tf=tv[j]; tv[j]=tv[j-1]; tv[j-1]=tf;
            int tii=ti[j]; ti[j]=ti[j-1]; ti[j-1]=tii;
        }
    }
}

// ---------------- top-8 approx (fp16 logits) + exact fp32 rescue -> top-4 ----------------
__global__ void __launch_bounds__(128)
topk_rescue(const __half* __restrict__ logits, const float* __restrict__ q,
            const float* __restrict__ k, float* __restrict__ topv, int* __restrict__ topi)
{
    const int m = blockIdx.x;
    const int tid = threadIdx.x;
    const __half2* p2 = reinterpret_cast<const __half2*>(logits + (long)m * Sdim);

    float tv[8]; int ti[8];
#pragma unroll
    for (int j=0;j<8;j++){ tv[j]=-1e30f; ti[j]=-1; }
    for (int j = tid; j < Sdim/2; j += 128){
        __half2 hv = p2[j];
        ins8(__low2float(hv),  2*j,   tv, ti);
        ins8(__high2float(hv), 2*j+1, tv, ti);
    }

    __shared__ float sv[128*8];
    __shared__ int   si[128*8];
#pragma unroll
    for (int j=0;j<8;j++){ sv[tid*8+j]=tv[j]; si[tid*8+j]=ti[j]; }
    __syncthreads();

    if (tid < 32){
        float mv[8]; int mi[8];
#pragma unroll
        for (int j=0;j<8;j++){ mv[j]=-1e30f; mi[j]=-1; }
        for (int s=0;s<4;s++){
            int base = (tid + s*32)*8;
#pragma unroll
            for (int j=0;j<8;j++) ins8(sv[base+j], si[base+j], mv, mi);
        }
#pragma unroll
        for (int j=0;j<8;j++){ sv[tid*8+j]=mv[j]; si[tid*8+j]=mi[j]; }
    }
    __syncthreads();

    __shared__ int cands[8];
    if (tid == 0){
        float rv[8]; int ri[8];
#pragma unroll
        for (int j=0;j<8;j++){ rv[j]=-1e30f; ri[j]=-1; }
        for (int c=0;c<32*8;c++) ins8(sv[c], si[c], rv, ri);
#pragma unroll
        for (int j=0;j<8;j++) cands[j] = ri[j];
    }
    __syncthreads();

    __shared__ float qrow[Hdim];
    const float* qr = q + (long)m*Hdim;
    for (int j = tid; j < Hdim; j += 128) qrow[j] = qr[j];
    __syncthreads();

    const int b = m >> 12;
    const int warp = tid >> 5, lane = tid & 31;
    __shared__ float exact[8];
#pragma unroll
    for (int cc=0; cc<2; cc++){
        int c = warp*2 + cc;
        const float* kr = k + ((long)b*Sdim + cands[c])*Hdim;
        float s = 0.f;
        for (int j = lane; j < Hdim; j += 32) s += qrow[j]*kr[j];
#pragma unroll
        for (int o=16;o>0;o>>=1) s += __shfl_down_sync(0xffffffffu, s, o);
        if (lane == 0) exact[c] = s * INV_SCALE;
    }
    __syncthreads();

    if (tid == 0){
        float rv[4] = {-1e30f,-1e30f,-1e30f,-1e30f};
        int   ri[4] = {-1,-1,-1,-1};
#pragma unroll
        for (int c=0;c<8;c++) ins4(exact[c], cands[c], rv, ri);
#pragma unroll
        for (int j=0;j<4;j++){ topv[m*4+j]=rv[j]; topi[m*4+j]=ri[j]; }
    }
}

// ---------------- softmax + gather-weighted V (fp16) -> fp16 routed ----------------
__global__ void __launch_bounds__(256)
route_kernel(const __half* __restrict__ v, const float* __restrict__ topv,
             const int* __restrict__ topi, const float* __restrict__ temp,
             __half* __restrict__ rh)
{
    const int m = blockIdx.x;
    const int b = m >> 12;
    const float t = temp[0];
    float v0 = topv[m*4+0], v1 = topv[m*4+1], v2 = topv[m*4+2], v3 = topv[m*4+3];
    float mx = fmaxf(fmaxf(v0,v1), fmaxf(v2,v3));
    float e0 = expf((v0-mx)/t), e1 = expf((v1-mx)/t);
    float e2 = expf((v2-mx)/t), e3 = expf((v3-mx)/t);
    float inv = 1.f/(e0+e1+e2+e3);
    e0*=inv; e1*=inv; e2*=inv; e3*=inv;

    const __half* vb = v + (long)b*Sdim*Hdim;
    int i0=topi[m*4+0], i1=topi[m*4+1], i2=topi[m*4+2], i3=topi[m*4+3];
    int c = threadIdx.x;    // 256 threads x 4 halves
    uint2 u0 = reinterpret_cast<const uint2*>(vb + (long)i0*Hdim)[c];
    uint2 u1 = reinterpret_cast<const uint2*>(vb + (long)i1*Hdim)[c];
    uint2 u2 = reinterpret_cast<const uint2*>(vb + (long)i2*Hdim)[c];
    uint2 u3 = reinterpret_cast<const uint2*>(vb + (long)i3*Hdim)[c];

    float o[4];
#pragma unroll
    for (int half_i=0; half_i<2; half_i++){
        uint32_t w0 = half_i ? u0.y : u0.x;
        uint32_t w1 = half_i ? u1.y : u1.x;
        uint32_t w2 = half_i ? u2.y : u2.x;
        uint32_t w3 = half_i ? u3.y : u3.x;
        __half2 h0 = *reinterpret_cast<__half2*>(&w0);
        __half2 h1 = *reinterpret_cast<__half2*>(&w1);
        __half2 h2 = *reinterpret_cast<__half2*>(&w2);
        __half2 h3 = *reinterpret_cast<__half2*>(&w3);
        o[half_i*2+0] = e0*__low2float(h0)  + e1*__low2float(h1)  + e2*__low2float(h2)  + e3*__low2float(h3);
        o[half_i*2+1] = e0*__high2float(h0) + e1*__high2float(h1) + e2*__high2float(h2) + e3*__high2float(h3);
    }
    long ob = (long)m*Hdim + c*4;
#pragma unroll
    for (int j=0;j<4;j++) rh[ob+j] = __float2half(o[j]);
}

// ---------------- LayerNorm (+gelu), fp16 in -> fp16 out(s) ----------------
template<int GELU>
__global__ void __launch_bounds__(256)
ln_kernel(const __half* __restrict__ in, const float* __restrict__ g,
          const float* __restrict__ b, __half* __restrict__ out1, int os1,
          __half* __restrict__ out2)
{
    const int m = blockIdx.x;
    const int c = threadIdx.x;
    uint2 xu = reinterpret_cast<const uint2*>(in + (long)m*Hdim)[c];
    __half2 hx0 = *reinterpret_cast<__half2*>(&xu.x);
    __half2 hx1 = *reinterpret_cast<__half2*>(&xu.y);
    float x0 = __low2float(hx0), x1 = __high2float(hx0);
    float x2 = __low2float(hx1), x3 = __high2float(hx1);
    float s  = x0 + x1 + x2 + x3;
    float ss = x0*x0 + x1*x1 + x2*x2 + x3*x3;
#pragma unroll
    for (int o=16;o>0;o>>=1){
        s  += __shfl_down_sync(0xffffffffu, s,  o);
        ss += __shfl_down_sync(0xffffffffu, ss, o);
    }
    __shared__ float red[2][8];
    int warp = c>>5, lane = c&31;
    if (lane==0){ red[0][warp]=s; red[1][warp]=ss; }
    __syncthreads();
    if (c==0){
        float S_=0.f, SS_=0.f;
#pragma unroll
        for (int w=0;w<8;w++){ S_+=red[0][w]; SS_+=red[1][w]; }
        red[0][0]=S_; red[1][0]=SS_;
    }
    __syncthreads();
    float mu  = red[0][0]*(1.f/Hdim);
    float var = red[1][0]*(1.f/Hdim) - mu*mu;
    float rsd = rsqrtf(var + LNEPS);
    float4 g4 = reinterpret_cast<const float4*>(g)[c];
    float4 b4 = reinterpret_cast<const float4*>(b)[c];
    float y[4];
    y[0] = (x0-mu)*rsd*g4.x + b4.x;
    y[1] = (x1-mu)*rsd*g4.y + b4.y;
    y[2] = (x2-mu)*rsd*g4.z + b4.z;
    y[3] = (x3-mu)*rsd*g4.w + b4.w;
    if (GELU){
#pragma unroll
        for (int j=0;j<4;j++) y[j] = 0.5f*y[j]*(1.f + erff(y[j]*0.70710678118f));
    }
    long o1 = (long)m*os1 + c*4;
#pragma unroll
    for (int j=0;j<4;j++) out1[o1+j] = __float2half(y[j]);
    if (out2){
        long o2 = (long)m*Hdim + c*4;
#pragma unroll
        for (int j=0;j<4;j++) out2[o2+j] = __float2half(y[j]);
    }
}

// ---------------- launch ----------------
extern "C" void kernel_launch(void* const* d_in, const int* in_sizes, int n_in,
                              void* d_out, int out_size)
{
    const float* x    = (const float*)d_in[0];
    const float* Wq   = (const float*)d_in[1];
    const float* bq   = (const float*)d_in[2];
    const float* Wk   = (const float*)d_in[3];
    const float* bk   = (const float*)d_in[4];
    const float* Wv   = (const float*)d_in[5];
    const float* bv   = (const float*)d_in[6];
    const float* Wc   = (const float*)d_in[7];
    const float* bc   = (const float*)d_in[8];
    const float* ln_g = (const float*)d_in[9];
    const float* ln_b = (const float*)d_in[10];
    const float* Wg1  = (const float*)d_in[11];
    const float* bg1  = (const float*)d_in[12];
    const float* gln_g= (const float*)d_in[13];
    const float* gln_b= (const float*)d_in[14];
    const float* Wg2  = (const float*)d_in[15];
    const float* bg2  = (const float*)d_in[16];
    const float* temp = (const float*)d_in[17];
    float* out = (float*)d_out;

    __nv_bfloat16 *xs_p, *wqk_p;
    __half *xcat_p, *qkh_p, *vh_p, *logh_p, *rh_p, *cpreh_p, *combh_p, *hpreh_p, *hs_p, *wh_p, *wg1h_p;
    float *qk32_p, *topv_p, *bqk_p;
    int *topi_p;
    cudaGetSymbolAddress((void**)&xs_p,    g_xs);
    cudaGetSymbolAddress((void**)&xcat_p,  g_xcat);
    cudaGetSymbolAddress((void**)&qk32_p,  g_qk32);
    cudaGetSymbolAddress((void**)&qkh_p,   g_qkh);
    cudaGetSymbolAddress((void**)&vh_p,    g_vh);
    cudaGetSymbolAddress((void**)&logh_p,  g_logh);
    cudaGetSymbolAddress((void**)&topv_p,  g_topv);
    cudaGetSymbolAddress((void**)&topi_p,  g_topi);
    cudaGetSymbolAddress((void**)&rh_p,    g_rh);
    cudaGetSymbolAddress((void**)&cpreh_p, g_cpreh);
    cudaGetSymbolAddress((void**)&combh_p, g_combh);
    cudaGetSymbolAddress((void**)&hpreh_p, g_hpreh);
    cudaGetSymbolAddress((void**)&hs_p,    g_hs);
    cudaGetSymbolAddress((void**)&wqk_p,   g_wqk);
    cudaGetSymbolAddress((void**)&wh_p,    g_wh);
    cudaGetSymbolAddress((void**)&wg1h_p,  g_wg1h);
    cudaGetSymbolAddress((void**)&bqk_p,   g_bqk);

    float* q_p = qk32_p;
    float* k_p = qk32_p + (long)MTOT*Hdim;
    __half* qh_p = qkh_p;
    __half* kh_p = qkh_p + (long)MTOT*Hdim;
    __half *wv_p = wh_p, *wc_p = wh_p + (long)Hdim*Hdim, *wg2_p = wh_p + 2*(long)Hdim*Hdim;

    // prep
    split_x_kernel<<<MTOT*Hdim/256, 256>>>(x, xs_p, xcat_p);
    prep_w_kernel<<<Hdim*Hdim/256, 256>>>(Wq, Wk, Wv, Wc, Wg1, Wg2, bq, bk,
                                          wqk_p, wv_p, wc_p, wg2_p, wg1h_p, bqk_p);

    dim3 gNN(Hdim/BNt, MTOT/BMt, 1);       // (8, 64)
    dim3 gQK(K2/BNt, MTOT/BMt, 1);         // (16, 64)
    dim3 gNT(Sdim/BNt, Sdim/BMt, Bdim);    // (32, 32, 2)

    const int smemNN = NSTAGE*(BMt*ASTR*2 + BKt*BSTRNN*2);   // 107520
    const int smemNT = NSTAGE*(BMt*ASTR*2 + BNt*ASTR*2);     // 110592

    cudaFuncSetAttribute((const void*)mma_gemm<false,7,false>, cudaFuncAttributeMaxDynamicSharedMemorySize, smemNN);
    cudaFuncSetAttribute((const void*)mma_gemm<false,4,true>,  cudaFuncAttributeMaxDynamicSharedMemorySize, smemNN);
    cudaFuncSetAttribute((const void*)mma_gemm<false,3,true>,  cudaFuncAttributeMaxDynamicSharedMemorySize, smemNN);
    cudaFuncSetAttribute((const void*)mma_gemm<true,2,true>,   cudaFuncAttributeMaxDynamicSharedMemorySize, smemNT);

    // fused q|k (bf16x3, K=3072, N=2048) -> fp32 q,k + fp16 qh,kh
    mma_gemm<false,7,false><<<gQK,256,smemNN>>>(xs_p, wqk_p, bqk_p, nullptr, nullptr,
                                   qk32_p, qkh_p, K3, K2, K3, K2, 0,0,0, 1.f);

    // v (fp16 single pass, K=1024) -> fp16
    mma_gemm<false,4,true><<<gNN,256,smemNN>>>((const __nv_bfloat16*)xcat_p, (const __nv_bfloat16*)wv_p,
                                   bv, nullptr, nullptr, vh_p, nullptr,
                                   Hdim, Hdim, K2, Hdim, 0,0,0, 1.f);

    // approx logits (fp16, K=1024) -> fp16 logits buffer
    mma_gemm<true,2,true><<<gNT,256,smemNT>>>(
                                  (const __nv_bfloat16*)qh_p, (const __nv_bfloat16*)kh_p,
                                  nullptr, nullptr, nullptr, logh_p, nullptr,
                                  Hdim, Sdim, Hdim, Hdim,
                                  (long)Sdim*Hdim, (long)Sdim*Hdim, (long)Sdim*Sdim, INV_SCALE);

    // top-8 approx -> exact fp32 rescue -> top-4
    topk_rescue<<<MTOT,128>>>(logh_p, q_p, k_p, topv_p, topi_p);
    route_kernel<<<MTOT,256>>>(vh_p, topv_p, topi_p, temp, rh_p);

    // cpre = routed @ Wc + bc (fp16); combined = LN(cpre) -> xcat second half + combh
    mma_gemm<false,4,true><<<gNN,256,smemNN>>>((const __nv_bfloat16*)rh_p, (const __nv_bfloat16*)wc_p,
                                   bc, nullptr, nullptr, cpreh_p, nullptr,
                                   Hdim, Hdim, Hdim, Hdim, 0,0,0, 1.f);
    ln_kernel<0><<<MTOT,256>>>(cpreh_p, ln_g, ln_b, xcat_p + Hdim, K2, combh_p);

    // hpre = [x|combined] @ Wg1 + bg1 (fp16, K=2048)
    mma_gemm<false,4,true><<<gNN,256,smemNN>>>((const __nv_bfloat16*)xcat_p, (const __nv_bfloat16*)wg1h_p,
                                   bg1, nullptr, nullptr, hpreh_p, nullptr,
                                   K2, Hdim, K2, Hdim, 0,0,0, 1.f);

    // h = gelu(LN(hpre)) -> fp16
    ln_kernel<1><<<MTOT,256>>>(hpreh_p, gln_g, gln_b, hs_p, Hdim, nullptr);

    // out = sigmoid(h @ Wg2 + bg2) * combined(fp16) + (1-s) * x
    mma_gemm<false,3,true><<<gNN,256,smemNN>>>((const __nv_bfloat16*)hs_p, (const __nv_bfloat16*)wg2_p,
                                   bg2, combh_p, x, out, nullptr,
                                   Hdim, Hdim, Hdim, Hdim, 0,0,0, 1.f);
}